// round 3
// baseline (speedup 1.0000x reference)
#include <cuda_runtime.h>
#include <math.h>

#define NB   10
#define NC   14
#define LC   19
#define NOBJ 256
#define B_   8
#define H_   96
#define W_   96
#define C_   (NB*LC)          /* 190 */
#define HW   (H_*W_)          /* 9216 */
#define HW4  (HW/4)           /* 2304 */
#define NCONF4 ((B_*NB*HW)/4) /* 184320 */
#define NRED 256              /* reducer blocks */

__device__ float    g_partials[NRED];
__device__ unsigned g_ctr  = 0;   // monotonic; multiple of 256 at each replay start
__device__ unsigned g_flag = 0;   // released by last reducer, consumed+reset by block 0

__device__ __forceinline__ float warp_bfly_sum(float x) {
    #pragma unroll
    for (int o = 16; o > 0; o >>= 1) x += __shfl_xor_sync(0xffffffffu, x, o);
    return x;
}

__global__ void __launch_bounds__(256, 1)
yolo_fused(const float* __restrict__ P, const float* __restrict__ T,
           const int* __restrict__ G, float* __restrict__ out) {

    // ======================= Reducer blocks (1..256) =======================
    if (blockIdx.x != 0) {
        __shared__ float wsum[8];
        float acc = 0.f;
        const int rb = blockIdx.x - 1;
        for (int e = rb * 256 + threadIdx.x; e < NCONF4; e += NRED * 256) {
            int p4  = e / HW4;              // (b, a) pair index 0..79
            int pos = e - p4 * HW4;
            int b = p4 / NB;
            int a = p4 - b * NB;
            int base4 = (b * C_ + a * LC) * HW4 + pos;
            float4 pv = __ldg(((const float4*)P) + base4);
            float4 tv = __ldg(((const float4*)T) + base4);
            float d0 = tv.x - pv.x, d1 = tv.y - pv.y;
            float d2 = tv.z - pv.z, d3 = tv.w - pv.w;
            acc += d0*d0 + d1*d1 + d2*d2 + d3*d3;
        }
        acc = warp_bfly_sum(acc);
        if ((threadIdx.x & 31) == 0) wsum[threadIdx.x >> 5] = acc;
        __syncthreads();
        if (threadIdx.x == 0) {
            float s = 0.f;
            #pragma unroll
            for (int w = 0; w < 8; ++w) s += wsum[w];
            g_partials[rb] = s;
            __threadfence();
            unsigned old = atomicAdd(&g_ctr, 1u);
            if ((old & 255u) == 255u) {      // last reducer of this replay
                __threadfence();
                atomicExch(&g_flag, 1u);     // release
            }
        }
        return;
    }

    // ======================= Sparse block (block 0) ========================
    __shared__ int sb[NOBJ], sg[NOBJ], sh[NOBJ], sw[NOBJ];
    __shared__ int v[NOBJ];
    __shared__ int proc[NOBJ];
    __shared__ int n_done;
    __shared__ float wred[4][8];   // [term][warp]
    __shared__ float pred8[8];

    const int i    = threadIdx.x;
    const int lane = i & 31;
    const int warp = i >> 5;

    sb[i] = G[4*i+0]; sg[i] = G[4*i+1]; sh[i] = G[4*i+2]; sw[i] = G[4*i+3];
    v[i] = 0; proc[i] = 0;
    if (i == 0) n_done = 0;
    __syncthreads();

    const int bi = sb[i], gi = sg[i], hi = sh[i], wi = sw[i];

    // ---- target components (channels g*19 + {0..4}) ----
    const int tb0 = bi*C_*HW + gi*LC*HW + hi*W_ + wi;
    const float tcv = __ldg(T + tb0);
    const float txv = __ldg(T + tb0 + 1*HW);
    const float tyv = __ldg(T + tb0 + 2*HW);
    const float twv = __ldg(T + tb0 + 3*HW);
    const float thv = __ldg(T + tb0 + 4*HW);
    const float t0 = txv - twv*0.5f, t1 = tyv - thv*0.5f;
    const float t2 = txv + twv*0.5f, t3 = tyv + thv*0.5f;
    const float ta = fabsf((t2 - t0) * (t3 - t1));

    // ---- IoU vs all 10 predicted anchors at (bi, hi, wi) ----
    const int pbb = bi*C_*HW + hi*W_ + wi;
    float iou[NB];
    #pragma unroll
    for (int a = 0; a < NB; ++a) {
        const int pc0 = pbb + a*LC*HW;
        float pxv = __ldg(P + pc0 + 1*HW), pyv = __ldg(P + pc0 + 2*HW);
        float pwv = __ldg(P + pc0 + 3*HW), phv = __ldg(P + pc0 + 4*HW);
        float p0 = pxv - pwv*0.5f, p1 = pyv - phv*0.5f;
        float p2 = pxv + pwv*0.5f, p3 = pyv + phv*0.5f;
        float x1 = fmaxf(t0, p0), y1 = fmaxf(t1, p1);
        float x2 = fminf(t2, p2), y2 = fminf(t3, p3);
        float inter = fmaxf(x2 - x1, 0.f) * fmaxf(y2 - y1, 0.f);
        float pa = fabsf((p2 - p0) * (p3 - p1));
        iou[a] = inter / (ta + pa - inter + 1e-6f);
    }

    // ---- conflict set: j with b_j==bi, g_j==hi, h_j==wi  (row read mI[gb,gh,gw,:]) ----
    unsigned cmask[8];
    #pragma unroll
    for (int wd = 0; wd < 8; ++wd) cmask[wd] = 0u;
    int cnt = 0;
    for (int j = 0; j < NOBJ; ++j) {
        if (sb[j] == bi && sg[j] == hi && sh[j] == wi) { cmask[j>>5] |= 1u << (j & 31); ++cnt; }
    }

    // ---- wave-ordered anchor assignment (exact sequential semantics) ----
    for (int round = 0; round < NOBJ; ++round) {
        bool ready = !proc[i];
        if (ready) {
            const int iw = i >> 5, ib = i & 31;
            for (int wd = 0; wd < 8 && ready; ++wd) {
                unsigned m = cmask[wd];
                if (wd > iw) m = 0u;
                else if (wd == iw) m &= (ib ? ((1u << ib) - 1u) : 0u);
                while (m) {
                    int j = (wd << 5) + __ffs(m) - 1;
                    if (!proc[j]) { ready = false; break; }
                    m &= m - 1;
                }
            }
        }
        __syncthreads();
        if (ready) {
            int cur = 0;
            #pragma unroll
            for (int a = 0; a < NB; ++a) {
                bool ne;
                if (a == 0 && cnt != W_) {
                    ne = false;   // some row entry is 0 -> all(row != 0) false
                } else {
                    ne = true;
                    for (int wd = 0; wd < 8 && ne; ++wd) {
                        unsigned m = cmask[wd];
                        while (m) {
                            int j = (wd << 5) + __ffs(m) - 1; m &= m - 1;
                            // j>i unprocessed -> 0; j==i -> mid-loop cur; j<i -> final v[j]
                            int vj = (j < i) ? v[j] : ((j == i) ? cur : 0);
                            if (a == 0) { if (vj == 0) { ne = false; break; } }
                            else        { if (vj == a) { ne = false; break; } }
                        }
                    }
                }
                if (ne && (float)cur < iou[a]) cur = a;
            }
            v[i] = cur;
        }
        __syncthreads();
        if (ready) { proc[i] = 1; atomicAdd(&n_done, 1); }
        __syncthreads();
        if (n_done == NOBJ) break;
    }

    const int sel = v[i];

    // sel_xy = maxI[b, g, h, h]: nonzero only if a valid grid sits at (bi, gi, hi, w=hi)
    int sxy = 0;
    for (int j = 0; j < NOBJ; ++j) {
        if (sb[j] == bi && sg[j] == gi && sh[j] == hi && sw[j] == hi) sxy = v[j];
    }

    // ---- loss gathers ----
    const float pxs = __ldg(P + pbb + (sxy*LC + 1)*HW);
    const float pys = __ldg(P + pbb + (sxy*LC + 2)*HW);
    const float pws = __ldg(P + pbb + (sel*LC + 3)*HW);
    const float phs = __ldg(P + pbb + (sel*LC + 4)*HW);
    const float pcs = __ldg(P + pbb + (sel*LC    )*HW);

    const float xl = (txv - pxs) * (txv - pxs);
    const float yl = (tyv - pys) * (tyv - pys);
    const float dw = sqrtf(fmaxf(twv, 0.f)) - sqrtf(fmaxf(pws, 0.f));
    const float dh = sqrtf(fmaxf(thv, 0.f)) - sqrtf(fmaxf(phs, 0.f));
    const float loc_i = xl + yl + dw*dw + dh*dh;
    const float co_i  = (tcv - pcs) * (tcv - pcs);

    // conf_nothing zero-set correction; dedup duplicate (b, sel, h, w) positions
    bool uniq = true;
    for (int j = 0; j < i; ++j) {
        if (sb[j] == bi && v[j] == sel && sh[j] == hi && sw[j] == wi) { uniq = false; break; }
    }
    float corr_i = 0.f;
    if (uniq) {
        float tsel = __ldg(T + pbb + (sel*LC)*HW);
        float d = tsel - pcs;
        corr_i = d * d;
    }

    // class loss: preds channel sel*19+5+c vs targets channel b*19+5+c (b as anchor index)
    float cls_i = 0.f;
    const int pcb = pbb + (sel*LC + 5)*HW;
    const int tcb = pbb + (bi *LC + 5)*HW;
    #pragma unroll
    for (int c = 0; c < NC; ++c) {
        float d = __ldg(P + pcb + c*HW) - __ldg(T + tcb + c*HW);
        cls_i += d * d;
    }
    cls_i *= (1.0f / NC);

    // ---- simultaneous warp-butterfly reductions of 4 sparse terms ----
    float r0 = warp_bfly_sum(loc_i);
    float r1 = warp_bfly_sum(co_i);
    float r2 = warp_bfly_sum(corr_i);
    float r3 = warp_bfly_sum(cls_i);
    if (lane == 0) { wred[0][warp] = r0; wred[1][warp] = r1; wred[2][warp] = r2; wred[3][warp] = r3; }

    // ---- wait for reducers (consume-and-reset flag; clean state per replay) ----
    __syncthreads();
    if (i == 0) {
        while (atomicCAS(&g_flag, 1u, 0u) != 1u) { __nanosleep(64); }
    }
    __syncthreads();
    __threadfence();   // acquire: order g_partials reads after flag observation

    // 256 partials: warp butterfly then 8-wide combine
    float pp = g_partials[i];
    pp = warp_bfly_sum(pp);
    if (lane == 0) pred8[warp] = pp;
    __syncthreads();

    if (i == 0) {
        float s_loc = 0.f, s_co = 0.f, s_corr = 0.f, s_cls = 0.f, s_tot = 0.f;
        #pragma unroll
        for (int w = 0; w < 8; ++w) {
            s_loc  += wred[0][w];
            s_co   += wred[1][w];
            s_corr += wred[2][w];
            s_cls  += wred[3][w];
            s_tot  += pred8[w];
        }
        const float n = (float)NOBJ;
        float localization = s_loc / n;
        float conf_obj     = s_co  / n;
        float conf_nothing = (s_tot - s_corr) / (float)(B_*NB*H_*W_);
        float class_loss   = s_cls / n;
        out[0] = 7.0f * localization + 5.0f * conf_obj + 5.0f * conf_nothing + class_loss;
    }
}

extern "C" void kernel_launch(void* const* d_in, const int* in_sizes, int n_in,
                              void* d_out, int out_size) {
    const float* P = (const float*)d_in[0];   // predictions (8,190,96,96) f32
    const float* T = (const float*)d_in[1];   // targets     (8,190,96,96) f32
    const int*   G = (const int*)d_in[2];     // valid_grids (256,4) i32
    float* out = (float*)d_out;
    yolo_fused<<<NRED + 1, 256>>>(P, T, G, out);
}

// round 5
// speedup vs baseline: 1.9160x; 1.9160x over previous
#include <cuda_runtime.h>
#include <math.h>

#define NB   10
#define NC   14
#define LC   19
#define NOBJ 256
#define B_   8
#define H_   96
#define W_   96
#define C_   (NB*LC)          /* 190 */
#define HW   (H_*W_)          /* 9216 */
#define HW4  (HW/4)           /* 2304 */
#define NCONF4 ((B_*NB*HW)/4) /* 184320 */
#define NRED 256              /* gather/reducer blocks */
#define SLOTS 64              /* padded from 60 */

// transposed per-object candidate data: g_t[slot*NOBJ + obj]
//  slot  0+a : iou[a]
//  slot 10+a : xy_loss candidate  (sxy == a)
//  slot 20+a : wh_loss candidate  (sel == a)
//  slot 30+a : conf_obj candidate (sel == a)
//  slot 40+a : corr candidate     (sel == a)
//  slot 50+a : class loss candidate (sel == a)
__device__ float    g_t[SLOTS * NOBJ];
__device__ float    g_partials[NRED];
__device__ unsigned g_gctr = 0, g_gflag = 0;   // gather+compute complete
__device__ unsigned g_ctr  = 0, g_flag  = 0;   // conf partials complete

__device__ __forceinline__ float warp_bfly_sum(float x) {
    #pragma unroll
    for (int o = 16; o > 0; o >>= 1) x += __shfl_xor_sync(0xffffffffu, x, o);
    return x;
}

__global__ void __launch_bounds__(256, 1)
yolo_fused(const float* __restrict__ P, const float* __restrict__ T,
           const int* __restrict__ G, float* __restrict__ out) {

    // ========== Gather + per-anchor compute + reducer blocks (1..256) ==========
    if (blockIdx.x != 0) {
        __shared__ int   sgeo[4];
        __shared__ float sg[240];     // staged raw values for this object
        __shared__ float wsum[8];
        const int rb = blockIdx.x - 1;      // object index
        const int t  = threadIdx.x;
        if (t < 4) sgeo[t] = G[4*rb + t];
        __syncthreads();
        const int bo = sgeo[0], go = sgeo[1], ho = sgeo[2], wo = sgeo[3];
        const int pbb = bo*C_*HW + ho*W_ + wo;
        const int tb0 = pbb + go*LC*HW;

        // one scattered load per thread into block smem
        // 0..4: target box; 8+a*5+c: pred box; 64+a: T conf chan a;
        // 80+a*14+c: pred class; 224+c: target class (channel b*19+5+c)
        if (t < 5)         sg[t]            = __ldg(T + tb0 + t*HW);
        else if (t < 55) { int k = t-5, a = k/5, c = k-a*5;
                           sg[8+k]          = __ldg(P + pbb + (a*LC + c)*HW); }
        else if (t < 65)   sg[64 + (t-55)]  = __ldg(T + pbb + (t-55)*LC*HW);
        else if (t < 205){ int k = t-65, a = k/14, c = k-a*14;
                           sg[80+k]         = __ldg(P + pbb + (a*LC + 5 + c)*HW); }
        else if (t < 219)  sg[224 + (t-205)]= __ldg(T + pbb + (bo*LC + 5 + (t-205))*HW);
        __syncthreads();

        // per-anchor candidate computation: thread a = 0..9
        if (t < NB) {
            const int a = t;
            const float tcv = sg[0], txv = sg[1], tyv = sg[2], twv = sg[3], thv = sg[4];
            const float t0 = txv - twv*0.5f, t1 = tyv - thv*0.5f;
            const float t2 = txv + twv*0.5f, t3 = tyv + thv*0.5f;
            const float ta = fabsf((t2 - t0) * (t3 - t1));
            const float pcv = sg[8+a*5+0];
            const float pxv = sg[8+a*5+1], pyv = sg[8+a*5+2];
            const float pwv = sg[8+a*5+3], phv = sg[8+a*5+4];
            const float p0 = pxv - pwv*0.5f, p1 = pyv - phv*0.5f;
            const float p2 = pxv + pwv*0.5f, p3 = pyv + phv*0.5f;
            float x1 = fmaxf(t0, p0), y1 = fmaxf(t1, p1);
            float x2 = fminf(t2, p2), y2 = fminf(t3, p3);
            float inter = fmaxf(x2 - x1, 0.f) * fmaxf(y2 - y1, 0.f);
            float pa = fabsf((p2 - p0) * (p3 - p1));
            const float iou = inter / (ta + pa - inter + 1e-6f);

            const float xy = (txv - pxv)*(txv - pxv) + (tyv - pyv)*(tyv - pyv);
            const float dwv = sqrtf(fmaxf(twv, 0.f)) - sqrtf(fmaxf(pwv, 0.f));
            const float dhv = sqrtf(fmaxf(thv, 0.f)) - sqrtf(fmaxf(phv, 0.f));
            const float wh = dwv*dwv + dhv*dhv;
            const float co = (tcv - pcv)*(tcv - pcv);
            const float cr = (sg[64+a] - pcv)*(sg[64+a] - pcv);
            float cls = 0.f;
            #pragma unroll
            for (int c = 0; c < NC; ++c) {
                float d = sg[80+a*14+c] - sg[224+c];
                cls += d*d;
            }
            cls *= (1.0f / NC);

            g_t[( 0+a)*NOBJ + rb] = iou;
            g_t[(10+a)*NOBJ + rb] = xy;
            g_t[(20+a)*NOBJ + rb] = wh;
            g_t[(30+a)*NOBJ + rb] = co;
            g_t[(40+a)*NOBJ + rb] = cr;
            g_t[(50+a)*NOBJ + rb] = cls;
        }
        __syncthreads();
        if (t == 0) {
            __threadfence();
            unsigned old = atomicAdd(&g_gctr, 1u);
            if ((old & 255u) == 255u) { __threadfence(); atomicExch(&g_gflag, 1u); }
        }

        // ---- conf-channel SSE slice ----
        float acc = 0.f;
        for (int e = rb * 256 + t; e < NCONF4; e += NRED * 256) {
            int p4  = e / HW4;
            int pos = e - p4 * HW4;
            int b = p4 / NB;
            int a = p4 - b * NB;
            int base4 = (b * C_ + a * LC) * HW4 + pos;
            float4 pv = __ldg(((const float4*)P) + base4);
            float4 tv = __ldg(((const float4*)T) + base4);
            float d0 = tv.x - pv.x, d1 = tv.y - pv.y;
            float d2 = tv.z - pv.z, d3 = tv.w - pv.w;
            acc += d0*d0 + d1*d1 + d2*d2 + d3*d3;
        }
        acc = warp_bfly_sum(acc);
        if ((t & 31) == 0) wsum[t >> 5] = acc;
        __syncthreads();
        if (t == 0) {
            float s = 0.f;
            #pragma unroll
            for (int w = 0; w < 8; ++w) s += wsum[w];
            g_partials[rb] = s;
            __threadfence();
            unsigned old = atomicAdd(&g_ctr, 1u);
            if ((old & 255u) == 255u) { __threadfence(); atomicExch(&g_flag, 1u); }
        }
        return;
    }

    // ======================= Sparse block (block 0) ========================
    __shared__ int skey[NOBJ];     // (b<<18)|(g<<14)|(h<<7)|w
    __shared__ int dkey[NOBJ];     // (b<<18)|(sel<<14)|(h<<7)|w
    __shared__ int v[NOBJ];
    __shared__ int proc[NOBJ];
    __shared__ int n_done;
    __shared__ float wred[4][8];
    __shared__ float pred8[8];

    const int i    = threadIdx.x;
    const int lane = i & 31;
    const int warp = i >> 5;

    const int bi = G[4*i+0], gi = G[4*i+1], hi = G[4*i+2], wi = G[4*i+3];
    skey[i] = (bi<<18) | (gi<<14) | (hi<<7) | wi;
    v[i] = 0; proc[i] = 0;
    if (i == 0) n_done = 0;
    __syncthreads();

    // conflict set {j : b_j==bi, g_j==hi, h_j==wi}; h,g <= 9 so packing exact
    const int ckey = (bi<<11) | (hi<<7) | wi;
    unsigned cmask[8];
    #pragma unroll
    for (int wd = 0; wd < 8; ++wd) cmask[wd] = 0u;
    int cnt = 0;
    #pragma unroll 4
    for (int j = 0; j < NOBJ; ++j) {
        if ((skey[j] >> 7) == ckey) { cmask[j>>5] |= 1u << (j & 31); ++cnt; }
    }

    // wait for gather/compute phase (consume-and-reset for graph replays)
    if (i == 0) { while (atomicCAS(&g_gflag, 1u, 0u) != 1u) { __nanosleep(32); } }
    __syncthreads();
    __threadfence();

    // coalesced IoU loads (one 128B line per warp per anchor)
    float iou[NB];
    #pragma unroll
    for (int a = 0; a < NB; ++a) iou[a] = g_t[a*NOBJ + i];

    // ---- wave-ordered anchor assignment (exact sequential semantics) ----
    for (int round = 0; round < NOBJ; ++round) {
        bool ready = !proc[i];
        if (ready) {
            const int iw = i >> 5, ib = i & 31;
            for (int wd = 0; wd < 8 && ready; ++wd) {
                unsigned m = cmask[wd];
                if (wd > iw) m = 0u;
                else if (wd == iw) m &= (ib ? ((1u << ib) - 1u) : 0u);
                while (m) {
                    int j = (wd << 5) + __ffs(m) - 1;
                    if (!proc[j]) { ready = false; break; }
                    m &= m - 1;
                }
            }
        }
        __syncthreads();
        if (ready) {
            int cur = 0;
            #pragma unroll
            for (int a = 0; a < NB; ++a) {
                bool ne;
                if (a == 0 && cnt != W_) {
                    ne = false;   // uncovered row entry is 0
                } else {
                    ne = true;
                    for (int wd = 0; wd < 8 && ne; ++wd) {
                        unsigned m = cmask[wd];
                        while (m) {
                            int j = (wd << 5) + __ffs(m) - 1; m &= m - 1;
                            // j>i unprocessed -> 0; j==i -> mid-loop cur; j<i -> final
                            int vj = (j < i) ? v[j] : ((j == i) ? cur : 0);
                            if (a == 0) { if (vj == 0) { ne = false; break; } }
                            else        { if (vj == a) { ne = false; break; } }
                        }
                    }
                }
                if (ne && (float)cur < iou[a]) cur = a;
            }
            v[i] = cur;
        }
        __syncthreads();
        if (ready) { proc[i] = 1; atomicAdd(&n_done, 1); }
        __syncthreads();
        if (n_done == NOBJ) break;
    }

    const int sel = v[i];
    dkey[i] = (bi<<18) | (sel<<14) | (hi<<7) | wi;
    __syncthreads();

    // sel_xy = maxI[b, g, h, h]
    const int xkey = (bi<<18) | (gi<<14) | (hi<<7) | hi;
    int sxy = 0;
    #pragma unroll 4
    for (int j = 0; j < NOBJ; ++j) {
        if (skey[j] == xkey) sxy = v[j];
    }

    // dedup duplicate (b, sel, h, w) zero-set cells
    bool uniq = true;
    const int mykey = dkey[i];
    for (int j = 0; j < i; ++j) {
        if (dkey[j] == mykey) { uniq = false; break; }
    }

    // candidate-indexed loads (mostly coalesced; few distinct sel per warp)
    const float loc_i  = g_t[(10+sxy)*NOBJ + i] + g_t[(20+sel)*NOBJ + i];
    const float co_i   = g_t[(30+sel)*NOBJ + i];
    const float corr_i = uniq ? g_t[(40+sel)*NOBJ + i] : 0.f;
    const float cls_i  = g_t[(50+sel)*NOBJ + i];

    float r0 = warp_bfly_sum(loc_i);
    float r1 = warp_bfly_sum(co_i);
    float r2 = warp_bfly_sum(corr_i);
    float r3 = warp_bfly_sum(cls_i);
    if (lane == 0) { wred[0][warp] = r0; wred[1][warp] = r1; wred[2][warp] = r2; wred[3][warp] = r3; }

    // wait for conf partials
    __syncthreads();
    if (i == 0) { while (atomicCAS(&g_flag, 1u, 0u) != 1u) { __nanosleep(32); } }
    __syncthreads();
    __threadfence();

    float pp = warp_bfly_sum(g_partials[i]);
    if (lane == 0) pred8[warp] = pp;
    __syncthreads();

    if (i == 0) {
        float s_loc = 0.f, s_co = 0.f, s_corr = 0.f, s_cls = 0.f, s_tot = 0.f;
        #pragma unroll
        for (int w = 0; w < 8; ++w) {
            s_loc  += wred[0][w];
            s_co   += wred[1][w];
            s_corr += wred[2][w];
            s_cls  += wred[3][w];
            s_tot  += pred8[w];
        }
        const float n = (float)NOBJ;
        float localization = s_loc / n;
        float conf_obj     = s_co  / n;
        float conf_nothing = (s_tot - s_corr) / (float)(B_*NB*H_*W_);
        float class_loss   = s_cls / n;
        out[0] = 7.0f * localization + 5.0f * conf_obj + 5.0f * conf_nothing + class_loss;
    }
}

extern "C" void kernel_launch(void* const* d_in, const int* in_sizes, int n_in,
                              void* d_out, int out_size) {
    const float* P = (const float*)d_in[0];   // predictions (8,190,96,96) f32
    const float* T = (const float*)d_in[1];   // targets     (8,190,96,96) f32
    const int*   G = (const int*)d_in[2];     // valid_grids (256,4) i32
    float* out = (float*)d_out;
    yolo_fused<<<NRED + 1, 256>>>(P, T, G, out);
}

// round 6
// speedup vs baseline: 2.2052x; 1.1509x over previous
#include <cuda_runtime.h>
#include <math.h>

#define NB   10
#define NC   14
#define LC   19
#define NOBJ 256
#define B_   8
#define H_   96
#define W_   96
#define C_   (NB*LC)          /* 190 */
#define HW   (H_*W_)          /* 9216 */
#define HW4  (HW/4)           /* 2304 */
#define NCONF4 ((B_*NB*HW)/4) /* 184320 */
#define NRED 256              /* gather/reducer blocks */
#define F4_PER_BLK 720        /* NCONF4 / NRED */
#define GATHER_ARR (NOBJ*NB)  /* 2560 gather arrivals per replay */
#define CONF_ARR   (NOBJ*8)   /* 2048 warp arrivals per replay (pow2) */

// transposed per-object candidate data: g_t[slot*NOBJ + obj]
//  slot  0+a : iou[a]
//  slot 10+a : xy_loss cand (sxy==a) | 20+a : wh (sel==a) | 30+a : conf_obj
//  slot 40+a : corr cand            | 50+a : class loss cand
__device__ float    g_t[64 * NOBJ];
__device__ float    g_partials[CONF_ARR];      // [obj*8 + warp]
__device__ unsigned g_gctr = 0, g_gflag = 0;   // gather complete
__device__ unsigned g_ctr  = 0, g_flag  = 0;   // conf partials complete

__device__ __forceinline__ float warp_bfly_sum(float x) {
    #pragma unroll
    for (int o = 16; o > 0; o >>= 1) x += __shfl_xor_sync(0xffffffffu, x, o);
    return x;
}

__global__ void __launch_bounds__(256, 1)
yolo_fused(const float* __restrict__ P, const float* __restrict__ T,
           const int* __restrict__ G, float* __restrict__ out) {

    // ========= Gather + per-anchor compute + conf reducer blocks (1..256) =========
    if (blockIdx.x != 0) {
        const int rb = blockIdx.x - 1;      // object index
        const int t  = threadIdx.x;

        // ---- per-anchor gather + candidate compute: threads 0..9, no barriers ----
        if (t < NB) {
            const int a = t;
            const int bo = __ldg(G + 4*rb + 0), go = __ldg(G + 4*rb + 1);
            const int ho = __ldg(G + 4*rb + 2), wo = __ldg(G + 4*rb + 3);
            const int pbb = bo*C_*HW + ho*W_ + wo;
            const int tb0 = pbb + go*LC*HW;
            const int ab  = pbb + a*LC*HW;

            // all loads independent -> single DRAM latency exposure
            const float tcv = __ldg(T + tb0);
            const float txv = __ldg(T + tb0 + 1*HW);
            const float tyv = __ldg(T + tb0 + 2*HW);
            const float twv = __ldg(T + tb0 + 3*HW);
            const float thv = __ldg(T + tb0 + 4*HW);
            const float pcv = __ldg(P + ab);
            const float pxv = __ldg(P + ab + 1*HW);
            const float pyv = __ldg(P + ab + 2*HW);
            const float pwv = __ldg(P + ab + 3*HW);
            const float phv = __ldg(P + ab + 4*HW);
            const float tca = __ldg(T + ab);          // target conf channel of anchor a
            float pcls[NC], tcls[NC];
            #pragma unroll
            for (int c = 0; c < NC; ++c) pcls[c] = __ldg(P + ab + (5 + c)*HW);
            #pragma unroll
            for (int c = 0; c < NC; ++c) tcls[c] = __ldg(T + pbb + (bo*LC + 5 + c)*HW);

            const float t0 = txv - twv*0.5f, t1 = tyv - thv*0.5f;
            const float t2 = txv + twv*0.5f, t3 = tyv + thv*0.5f;
            const float ta = fabsf((t2 - t0) * (t3 - t1));
            const float p0 = pxv - pwv*0.5f, p1 = pyv - phv*0.5f;
            const float p2 = pxv + pwv*0.5f, p3 = pyv + phv*0.5f;
            float x1 = fmaxf(t0, p0), y1 = fmaxf(t1, p1);
            float x2 = fminf(t2, p2), y2 = fminf(t3, p3);
            float inter = fmaxf(x2 - x1, 0.f) * fmaxf(y2 - y1, 0.f);
            float pa = fabsf((p2 - p0) * (p3 - p1));
            const float iou = inter / (ta + pa - inter + 1e-6f);

            const float xy = (txv - pxv)*(txv - pxv) + (tyv - pyv)*(tyv - pyv);
            const float dwv = sqrtf(fmaxf(twv, 0.f)) - sqrtf(fmaxf(pwv, 0.f));
            const float dhv = sqrtf(fmaxf(thv, 0.f)) - sqrtf(fmaxf(phv, 0.f));
            const float wh = dwv*dwv + dhv*dhv;
            const float co = (tcv - pcv)*(tcv - pcv);
            const float cr = (tca - pcv)*(tca - pcv);
            float cls = 0.f;
            #pragma unroll
            for (int c = 0; c < NC; ++c) { float d = pcls[c] - tcls[c]; cls += d*d; }
            cls *= (1.0f / NC);

            g_t[( 0+a)*NOBJ + rb] = iou;
            g_t[(10+a)*NOBJ + rb] = xy;
            g_t[(20+a)*NOBJ + rb] = wh;
            g_t[(30+a)*NOBJ + rb] = co;
            g_t[(40+a)*NOBJ + rb] = cr;
            g_t[(50+a)*NOBJ + rb] = cls;
            __threadfence();
            unsigned old = atomicAdd(&g_gctr, 1u);
            if ((old % (unsigned)GATHER_ARR) == (unsigned)(GATHER_ARR - 1)) {
                atomicExch(&g_gflag, 1u);
            }
        }

        // ---- conf-channel SSE slice: fully unrolled, all loads batched ----
        {
            const int ebase = rb * F4_PER_BLK;
            float4 pv[3], tv[3];
            const bool on2 = (t < (F4_PER_BLK - 512));   // t < 208
            #pragma unroll
            for (int k = 0; k < 3; ++k) {
                if (k < 2 || on2) {
                    int e   = ebase + (k << 8) + t;
                    int p4  = e / HW4;
                    int pos = e - p4 * HW4;
                    int b = p4 / NB;
                    int a = p4 - b * NB;
                    int base4 = (b * C_ + a * LC) * HW4 + pos;
                    pv[k] = __ldg(((const float4*)P) + base4);
                    tv[k] = __ldg(((const float4*)T) + base4);
                }
            }
            float acc = 0.f;
            #pragma unroll
            for (int k = 0; k < 3; ++k) {
                if (k < 2 || on2) {
                    float d0 = tv[k].x - pv[k].x, d1 = tv[k].y - pv[k].y;
                    float d2 = tv[k].z - pv[k].z, d3 = tv[k].w - pv[k].w;
                    acc += d0*d0 + d1*d1 + d2*d2 + d3*d3;
                }
            }
            acc = warp_bfly_sum(acc);
            if ((t & 31) == 0) {
                g_partials[rb*8 + (t >> 5)] = acc;
                __threadfence();
                unsigned old = atomicAdd(&g_ctr, 1u);
                if ((old & (unsigned)(CONF_ARR - 1)) == (unsigned)(CONF_ARR - 1)) {
                    atomicExch(&g_flag, 1u);
                }
            }
        }
        return;
    }

    // ======================= Sparse block (block 0) ========================
    __shared__ int skey[NOBJ];     // (b<<18)|(g<<14)|(h<<7)|w
    __shared__ int dkey[NOBJ];     // (b<<18)|(sel<<14)|(h<<7)|w
    __shared__ int v[NOBJ];
    __shared__ int proc[NOBJ];
    __shared__ int n_done;
    __shared__ float wred[4][8];
    __shared__ float pred8[8];

    const int i    = threadIdx.x;
    const int lane = i & 31;
    const int warp = i >> 5;

    const int bi = __ldg(G + 4*i+0), gi = __ldg(G + 4*i+1);
    const int hi = __ldg(G + 4*i+2), wi = __ldg(G + 4*i+3);
    skey[i] = (bi<<18) | (gi<<14) | (hi<<7) | wi;
    v[i] = 0; proc[i] = 0;
    if (i == 0) n_done = 0;
    __syncthreads();

    // conflict set {j : b_j==bi, g_j==hi, h_j==wi}; break-free, pipelined LDS
    const int ckey = (bi<<11) | (hi<<7) | wi;
    unsigned cmask[8];
    #pragma unroll
    for (int wd = 0; wd < 8; ++wd) cmask[wd] = 0u;
    int cnt = 0;
    #pragma unroll 8
    for (int j = 0; j < NOBJ; ++j) {
        if ((skey[j] >> 7) == ckey) { cmask[j>>5] |= 1u << (j & 31); ++cnt; }
    }

    // wait for gather/compute phase (consume-and-reset for graph replays)
    if (i == 0) { while (atomicCAS(&g_gflag, 1u, 0u) != 1u) { __nanosleep(32); } }
    __syncthreads();
    __threadfence();

    // coalesced IoU loads (one 128B line per warp per anchor)
    float iou[NB];
    #pragma unroll
    for (int a = 0; a < NB; ++a) iou[a] = g_t[a*NOBJ + i];

    // ---- wave-ordered anchor assignment (exact sequential semantics) ----
    for (int round = 0; round < NOBJ; ++round) {
        bool ready = !proc[i];
        if (ready) {
            const int iw = i >> 5, ib = i & 31;
            for (int wd = 0; wd < 8 && ready; ++wd) {
                unsigned m = cmask[wd];
                if (wd > iw) m = 0u;
                else if (wd == iw) m &= (ib ? ((1u << ib) - 1u) : 0u);
                while (m) {
                    int j = (wd << 5) + __ffs(m) - 1;
                    if (!proc[j]) { ready = false; break; }
                    m &= m - 1;
                }
            }
        }
        __syncthreads();
        if (ready) {
            int cur = 0;
            #pragma unroll
            for (int a = 0; a < NB; ++a) {
                bool ne;
                if (a == 0 && cnt != W_) {
                    ne = false;   // uncovered row entry is 0 -> all(row != 0) false
                } else {
                    ne = true;
                    for (int wd = 0; wd < 8 && ne; ++wd) {
                        unsigned m = cmask[wd];
                        while (m) {
                            int j = (wd << 5) + __ffs(m) - 1; m &= m - 1;
                            // j>i unprocessed -> 0; j==i -> mid-loop cur; j<i -> final
                            int vj = (j < i) ? v[j] : ((j == i) ? cur : 0);
                            if (a == 0) { if (vj == 0) { ne = false; break; } }
                            else        { if (vj == a) { ne = false; break; } }
                        }
                    }
                }
                if (ne && (float)cur < iou[a]) cur = a;
            }
            v[i] = cur;
        }
        __syncthreads();
        if (ready) { proc[i] = 1; atomicAdd(&n_done, 1); }
        __syncthreads();
        if (n_done == NOBJ) break;
    }

    const int sel = v[i];
    dkey[i] = (bi<<18) | (sel<<14) | (hi<<7) | wi;
    __syncthreads();

    // sel_xy = maxI[b, g, h, h]; break-free pipelined scan
    const int xkey = (bi<<18) | (gi<<14) | (hi<<7) | hi;
    int sxy = 0;
    #pragma unroll 8
    for (int j = 0; j < NOBJ; ++j) {
        if (skey[j] == xkey) sxy = v[j];
    }

    // dedup duplicate (b, sel, h, w) zero-set cells; break-free full scan
    const int mykey = dkey[i];
    int dup = 0;
    #pragma unroll 8
    for (int j = 0; j < NOBJ; ++j) {
        dup |= (j < i) & (dkey[j] == mykey);
    }

    // candidate-indexed loads (few distinct sel per warp -> few lines)
    const float loc_i  = g_t[(10+sxy)*NOBJ + i] + g_t[(20+sel)*NOBJ + i];
    const float co_i   = g_t[(30+sel)*NOBJ + i];
    const float corr_i = dup ? 0.f : g_t[(40+sel)*NOBJ + i];
    const float cls_i  = g_t[(50+sel)*NOBJ + i];

    float r0 = warp_bfly_sum(loc_i);
    float r1 = warp_bfly_sum(co_i);
    float r2 = warp_bfly_sum(corr_i);
    float r3 = warp_bfly_sum(cls_i);
    if (lane == 0) { wred[0][warp] = r0; wred[1][warp] = r1; wred[2][warp] = r2; wred[3][warp] = r3; }

    // wait for conf partials
    __syncthreads();
    if (i == 0) { while (atomicCAS(&g_flag, 1u, 0u) != 1u) { __nanosleep(32); } }
    __syncthreads();
    __threadfence();

    // 2048 partials: 8 per thread (fixed order), butterfly, 8-wide combine
    float pp = 0.f;
    #pragma unroll
    for (int k = 0; k < 8; ++k) pp += g_partials[i*8 + k];
    pp = warp_bfly_sum(pp);
    if (lane == 0) pred8[warp] = pp;
    __syncthreads();

    if (i == 0) {
        float s_loc = 0.f, s_co = 0.f, s_corr = 0.f, s_cls = 0.f, s_tot = 0.f;
        #pragma unroll
        for (int w = 0; w < 8; ++w) {
            s_loc  += wred[0][w];
            s_co   += wred[1][w];
            s_corr += wred[2][w];
            s_cls  += wred[3][w];
            s_tot  += pred8[w];
        }
        const float n = (float)NOBJ;
        float localization = s_loc / n;
        float conf_obj     = s_co  / n;
        float conf_nothing = (s_tot - s_corr) / (float)(B_*NB*H_*W_);
        float class_loss   = s_cls / n;
        out[0] = 7.0f * localization + 5.0f * conf_obj + 5.0f * conf_nothing + class_loss;
    }
}

extern "C" void kernel_launch(void* const* d_in, const int* in_sizes, int n_in,
                              void* d_out, int out_size) {
    const float* P = (const float*)d_in[0];   // predictions (8,190,96,96) f32
    const float* T = (const float*)d_in[1];   // targets     (8,190,96,96) f32
    const int*   G = (const int*)d_in[2];     // valid_grids (256,4) i32
    float* out = (float*)d_out;
    yolo_fused<<<NRED + 1, 256>>>(P, T, G, out);
}

// round 17
// speedup vs baseline: 2.3641x; 1.0721x over previous
#include <cuda_runtime.h>
#include <math.h>

#define NB   10
#define NC   14
#define LC   19
#define NOBJ 256
#define B_   8
#define H_   96
#define W_   96
#define C_   (NB*LC)          /* 190 */
#define HW   (H_*W_)          /* 9216 */
#define HW4  (HW/4)           /* 2304 */
#define NCONF4 ((B_*NB*HW)/4) /* 184320 */
#define NRED 256              /* gather/reducer blocks */
#define F4_PER_BLK 720        /* NCONF4 / NRED */

// transposed per-object candidate data: g_t[slot*NOBJ + obj]
//  slot  0+a : iou[a]
//  slot 10+a : xy cand (sxy==a) | 20+a : wh (sel==a) | 30+a : conf_obj
//  slot 40+a : corr cand        | 50+a : class loss cand
__device__ float              g_t[64 * NOBJ];
__device__ unsigned long long g_conf[NRED];    // payload (lo 32) + flag (hi 32), single 8B word
__device__ unsigned           g_gdone[NRED];   // per-object gather-complete flag

__device__ __forceinline__ float warp_bfly_sum(float x) {
    #pragma unroll
    for (int o = 16; o > 0; o >>= 1) x += __shfl_xor_sync(0xffffffffu, x, o);
    return x;
}

__global__ void __launch_bounds__(256, 1)
yolo_fused(const float* __restrict__ P, const float* __restrict__ T,
           const int* __restrict__ G, float* __restrict__ out) {

    // ========= Gather + per-anchor compute + conf reducer blocks (1..256) =========
    if (blockIdx.x != 0) {
        __shared__ float wsum[8];
        const int rb = blockIdx.x - 1;      // object index
        const int t  = threadIdx.x;

        // ---- per-anchor gather + candidate compute: lanes 0..9 of warp 0 ----
        if (t < 32) {
            if (t < NB) {
                const int a = t;
                const int4 g4 = __ldg(((const int4*)G) + rb);
                const int bo = g4.x, go = g4.y, ho = g4.z, wo = g4.w;
                const int pbb = bo*C_*HW + ho*W_ + wo;
                const int tb0 = pbb + go*LC*HW;
                const int ab  = pbb + a*LC*HW;

                // all loads independent -> single DRAM latency exposure
                const float tcv = __ldg(T + tb0);
                const float txv = __ldg(T + tb0 + 1*HW);
                const float tyv = __ldg(T + tb0 + 2*HW);
                const float twv = __ldg(T + tb0 + 3*HW);
                const float thv = __ldg(T + tb0 + 4*HW);
                const float pcv = __ldg(P + ab);
                const float pxv = __ldg(P + ab + 1*HW);
                const float pyv = __ldg(P + ab + 2*HW);
                const float pwv = __ldg(P + ab + 3*HW);
                const float phv = __ldg(P + ab + 4*HW);
                const float tca = __ldg(T + ab);      // target conf channel of anchor a
                float pcls[NC], tcls[NC];
                #pragma unroll
                for (int c = 0; c < NC; ++c) pcls[c] = __ldg(P + ab + (5 + c)*HW);
                #pragma unroll
                for (int c = 0; c < NC; ++c) tcls[c] = __ldg(T + pbb + (bo*LC + 5 + c)*HW);

                const float t0 = txv - twv*0.5f, t1 = tyv - thv*0.5f;
                const float t2 = txv + twv*0.5f, t3 = tyv + thv*0.5f;
                const float ta = fabsf((t2 - t0) * (t3 - t1));
                const float p0 = pxv - pwv*0.5f, p1 = pyv - phv*0.5f;
                const float p2 = pxv + pwv*0.5f, p3 = pyv + phv*0.5f;
                float x1 = fmaxf(t0, p0), y1 = fmaxf(t1, p1);
                float x2 = fminf(t2, p2), y2 = fminf(t3, p3);
                float inter = fmaxf(x2 - x1, 0.f) * fmaxf(y2 - y1, 0.f);
                float pa = fabsf((p2 - p0) * (p3 - p1));
                const float iou = inter / (ta + pa - inter + 1e-6f);

                const float xy = (txv - pxv)*(txv - pxv) + (tyv - pyv)*(tyv - pyv);
                const float dwv = sqrtf(fmaxf(twv, 0.f)) - sqrtf(fmaxf(pwv, 0.f));
                const float dhv = sqrtf(fmaxf(thv, 0.f)) - sqrtf(fmaxf(phv, 0.f));
                const float wh = dwv*dwv + dhv*dhv;
                const float co = (tcv - pcv)*(tcv - pcv);
                const float cr = (tca - pcv)*(tca - pcv);
                float cls = 0.f;
                #pragma unroll
                for (int c = 0; c < NC; ++c) { float d = pcls[c] - tcls[c]; cls += d*d; }
                cls *= (1.0f / NC);

                float* gt = g_t + a*NOBJ + rb;
                gt[ 0*NOBJ] = iou;
                gt[10*NOBJ] = xy;
                gt[20*NOBJ] = wh;
                gt[30*NOBJ] = co;
                gt[40*NOBJ] = cr;
                gt[50*NOBJ] = cls;
                __threadfence();    // release: this lane's g_t writes visible before flag
            }
            __syncwarp();
            if (t == 0) *((volatile unsigned*)&g_gdone[rb]) = 1u;   // per-object flag, no atomics
        }

        // ---- conf-channel SSE slice: fully unrolled, all loads batched ----
        {
            const int ebase = rb * F4_PER_BLK;
            float4 pv[3], tv[3];
            const bool on2 = (t < (F4_PER_BLK - 512));   // t < 208
            #pragma unroll
            for (int k = 0; k < 3; ++k) {
                if (k < 2 || on2) {
                    int e   = ebase + (k << 8) + t;
                    int p4  = e / HW4;
                    int pos = e - p4 * HW4;
                    int b = p4 / NB;
                    int a = p4 - b * NB;
                    int base4 = (b * C_ + a * LC) * HW4 + pos;
                    pv[k] = __ldg(((const float4*)P) + base4);
                    tv[k] = __ldg(((const float4*)T) + base4);
                }
            }
            float acc = 0.f;
            #pragma unroll
            for (int k = 0; k < 3; ++k) {
                if (k < 2 || on2) {
                    float d0 = tv[k].x - pv[k].x, d1 = tv[k].y - pv[k].y;
                    float d2 = tv[k].z - pv[k].z, d3 = tv[k].w - pv[k].w;
                    acc += d0*d0 + d1*d1 + d2*d2 + d3*d3;
                }
            }
            acc = warp_bfly_sum(acc);
            if ((t & 31) == 0) wsum[t >> 5] = acc;
            __syncthreads();
            if (t == 0) {
                float s = 0.f;
                #pragma unroll
                for (int w = 0; w < 8; ++w) s += wsum[w];
                // payload + flag in ONE 8-byte word -> single st.volatile.u64, naturally atomic
                unsigned long long word =
                    ((unsigned long long)1u << 32) | (unsigned long long)__float_as_uint(s);
                *((volatile unsigned long long*)&g_conf[rb]) = word;
            }
        }
        return;
    }

    // ======================= Sparse block (block 0) ========================
    __shared__ int skey[NOBJ];     // (b<<18)|(g<<14)|(h<<7)|w
    __shared__ int dkey[NOBJ];     // (b<<18)|(sel<<14)|(h<<7)|w
    __shared__ int v[NOBJ];
    __shared__ int proc[NOBJ];
    __shared__ int n_done;
    __shared__ float wred[4][8];
    __shared__ float pred8[8];

    const int i    = threadIdx.x;
    const int lane = i & 31;
    const int warp = i >> 5;

    const int4 g4 = __ldg(((const int4*)G) + i);
    const int bi = g4.x, gi = g4.y, hi = g4.z, wi = g4.w;
    skey[i] = (bi<<18) | (gi<<14) | (hi<<7) | wi;
    v[i] = 0; proc[i] = 0;
    if (i == 0) n_done = 0;
    __syncthreads();

    // conflict set {j : b_j==bi, g_j==hi, h_j==wi}; break-free, pipelined LDS
    const int ckey = (bi<<11) | (hi<<7) | wi;
    unsigned cmask[8];
    #pragma unroll
    for (int wd = 0; wd < 8; ++wd) cmask[wd] = 0u;
    int cnt = 0;
    #pragma unroll 8
    for (int j = 0; j < NOBJ; ++j) {
        if ((skey[j] >> 7) == ckey) { cmask[j>>5] |= 1u << (j & 31); ++cnt; }
    }

    // ---- wait for gather phase: each thread polls only its own object's flag ----
    {
        volatile unsigned* gd = (volatile unsigned*)&g_gdone[i];
        while (*gd == 0u) { __nanosleep(64); }
    }
    __threadfence();          // acquire: order g_t reads after flag observation
    g_gdone[i] = 0u;          // reset for next graph replay (no later writers this replay)

    // coalesced IoU loads (one 128B line per warp per anchor)
    float iou[NB];
    #pragma unroll
    for (int a = 0; a < NB; ++a) iou[a] = g_t[a*NOBJ + i];

    // ---- wave-ordered anchor assignment (exact sequential semantics) ----
    for (int round = 0; round < NOBJ; ++round) {
        bool ready = !proc[i];
        if (ready) {
            const int iw = i >> 5, ib = i & 31;
            for (int wd = 0; wd < 8 && ready; ++wd) {
                unsigned m = cmask[wd];
                if (wd > iw) m = 0u;
                else if (wd == iw) m &= (ib ? ((1u << ib) - 1u) : 0u);
                while (m) {
                    int j = (wd << 5) + __ffs(m) - 1;
                    if (!proc[j]) { ready = false; break; }
                    m &= m - 1;
                }
            }
        }
        __syncthreads();
        if (ready) {
            int cur = 0;
            #pragma unroll
            for (int a = 0; a < NB; ++a) {
                bool ne;
                if (a == 0 && cnt != W_) {
                    ne = false;   // uncovered row entry is 0 -> all(row != 0) false
                } else {
                    ne = true;
                    for (int wd = 0; wd < 8 && ne; ++wd) {
                        unsigned m = cmask[wd];
                        while (m) {
                            int j = (wd << 5) + __ffs(m) - 1; m &= m - 1;
                            // j>i unprocessed -> 0; j==i -> mid-loop cur; j<i -> final
                            int vj = (j < i) ? v[j] : ((j == i) ? cur : 0);
                            if (a == 0) { if (vj == 0) { ne = false; break; } }
                            else        { if (vj == a) { ne = false; break; } }
                        }
                    }
                }
                if (ne && (float)cur < iou[a]) cur = a;
            }
            v[i] = cur;
        }
        __syncthreads();
        if (ready) { proc[i] = 1; atomicAdd(&n_done, 1); }
        __syncthreads();
        if (n_done == NOBJ) break;
    }

    const int sel = v[i];
    dkey[i] = (bi<<18) | (sel<<14) | (hi<<7) | wi;
    __syncthreads();

    // merged scan: sel_xy = maxI[b,g,h,h] AND dedup of (b,sel,h,w) zero-set cells
    const int xkey  = (bi<<18) | (gi<<14) | (hi<<7) | hi;
    const int mykey = dkey[i];
    int sxy = 0, dup = 0;
    #pragma unroll 8
    for (int j = 0; j < NOBJ; ++j) {
        if (skey[j] == xkey) sxy = v[j];
        dup |= (j < i) & (dkey[j] == mykey);
    }

    // candidate-indexed loads (few distinct sel per warp -> few lines)
    const float loc_i  = g_t[(10+sxy)*NOBJ + i] + g_t[(20+sel)*NOBJ + i];
    const float co_i   = g_t[(30+sel)*NOBJ + i];
    const float corr_i = dup ? 0.f : g_t[(40+sel)*NOBJ + i];
    const float cls_i  = g_t[(50+sel)*NOBJ + i];

    float r0 = warp_bfly_sum(loc_i);
    float r1 = warp_bfly_sum(co_i);
    float r2 = warp_bfly_sum(corr_i);
    float r3 = warp_bfly_sum(cls_i);
    if (lane == 0) { wred[0][warp] = r0; wred[1][warp] = r1; wred[2][warp] = r2; wred[3][warp] = r3; }

    // ---- wait for conf partials: payload+flag share one 8B word per object ----
    float pp;
    {
        volatile unsigned long long* gc = (volatile unsigned long long*)&g_conf[i];
        unsigned long long w = *gc;
        while ((w >> 32) == 0ull) { __nanosleep(64); w = *gc; }
        pp = __uint_as_float((unsigned)(w & 0xffffffffull));
        *gc = 0ull;   // reset for next replay
    }
    pp = warp_bfly_sum(pp);
    if (lane == 0) pred8[warp] = pp;
    __syncthreads();

    if (i == 0) {
        float s_loc = 0.f, s_co = 0.f, s_corr = 0.f, s_cls = 0.f, s_tot = 0.f;
        #pragma unroll
        for (int w = 0; w < 8; ++w) {
            s_loc  += wred[0][w];
            s_co   += wred[1][w];
            s_corr += wred[2][w];
            s_cls  += wred[3][w];
            s_tot  += pred8[w];
        }
        const float n = (float)NOBJ;
        float localization = s_loc / n;
        float conf_obj     = s_co  / n;
        float conf_nothing = (s_tot - s_corr) / (float)(B_*NB*H_*W_);
        float class_loss   = s_cls / n;
        out[0] = 7.0f * localization + 5.0f * conf_obj + 5.0f * conf_nothing + class_loss;
    }
}

extern "C" void kernel_launch(void* const* d_in, const int* in_sizes, int n_in,
                              void* d_out, int out_size) {
    const float* P = (const float*)d_in[0];   // predictions (8,190,96,96) f32
    const float* T = (const float*)d_in[1];   // targets     (8,190,96,96) f32
    const int*   G = (const int*)d_in[2];     // valid_grids (256,4) i32
    float* out = (float*)d_out;
    yolo_fused<<<NRED + 1, 256>>>(P, T, G, out);
}